// round 8
// baseline (speedup 1.0000x reference)
#include <cuda_runtime.h>
#include <cstdint>

#define BB 32
#define LL 128
#define FF 128
#define RR 4096
#define HH (RR >> 1)
#define NN 262144
#define NGROUPS (BB * RR)      // 131072
#define CAP 32

// Scratch (allocation-free: __device__ globals).
__device__ int  g_cnt[NGROUPS];
__device__ int2 g_ac[NGROUPS * CAP];   // (e, coeff) car (j even) / cdr (j odd)
__device__ int2 g_ce[NGROUPS * CAP];   // (e, d2*w2)  cons -> even rows (j < H only)
__device__ int2 g_co[NGROUPS * CAP];   // (e, d2*w3)  cons -> odd rows  (j < H only)

__device__ __forceinline__ void acc_fma(float4& a, float c, const float4& v) {
    a.x = fmaf(c, v.x, a.x); a.y = fmaf(c, v.y, a.y);
    a.z = fmaf(c, v.z, a.z); a.w = fmaf(c, v.w, a.w);
}

// ---------------------------------------------------------------------------
// Kernel 1: one thread per element — inverted index with embedded coefficients.
__global__ void dti_build_kernel(const float4* __restrict__ arg_w,
                                 const float*  __restrict__ op_dist,
                                 const int* __restrict__ batch_idx,
                                 const int* __restrict__ slot_idx,
                                 const int* __restrict__ role_idx,
                                 int n) {
    int e = blockIdx.x * blockDim.x + threadIdx.x;
    if (e >= n) return;
    int b = __ldg(batch_idx + e);
    int s = __ldg(slot_idx + e);
    int j = __ldg(role_idx + e);
    float4 w = __ldg(arg_w + b * LL + s);
    float d0 = __ldg(op_dist + b * 3 + 0);
    float d1 = __ldg(op_dist + b * 3 + 1);
    float d2 = __ldg(op_dist + b * 3 + 2);
    int key = (b << 12) + j;
    int pos = atomicAdd(&g_cnt[key], 1);
    if (pos < CAP) {
        int idx = key * CAP + pos;
        float cac = (j & 1) ? d1 * w.y : d0 * w.x;
        g_ac[idx] = make_int2(e, __float_as_int(cac));
        if (j < HH) {
            g_ce[idx] = make_int2(e, __float_as_int(d2 * w.z));
            g_co[idx] = make_int2(e, __float_as_int(d2 * w.w));
        }
    }
}

// ---------------------------------------------------------------------------
// Kernel 2: all output rows, no atomics, no init pass.
//   warps [0, 65536):      one warp per LOW row (rr < H): cons + car + cdr
//                          merged into ONE strip-4 loop; only the value load
//                          is a gather (coeffs ride in the lists).
//   warps [65536, 98304):  one warp per HIGH row pair (cons only).
__global__ __launch_bounds__(256)
void dti_out_kernel(const float4* __restrict__ mem,
                    const float4* __restrict__ root_filler,
                    const float*  __restrict__ op_dist,
                    float4* __restrict__ out) {
    int wid = (blockIdx.x * blockDim.x + threadIdx.x) >> 5;
    int lane = threadIdx.x & 31;

    if (wid < BB * HH) {
        // ---------------- low row: rr in [0, H) ----------------
        int b = wid >> 11;
        int rr = wid & (HH - 1);
        int gbase = b << 12;
        bool odd = (rr & 1);

        // independent up-front coalesced loads (one latency level)
        int gc = gbase + (rr >> 1);
        int cntc = min(__ldg(&g_cnt[gc]), CAP);
        const int2* consList = odd ? g_co : g_ce;
        int2 cons = __ldg(consList + gc * CAP + lane);
        int2 c2 = __ldg((const int2*)&g_cnt[gbase + 2 * rr]);
        int sbA = (gbase + 2 * rr) * CAP;
        int sbB = sbA + CAP;
        int2 eA = __ldg(&g_ac[sbA + lane]);
        int2 eB = __ldg(&g_ac[sbB + lane]);
        int cnta = min(c2.x, CAP);
        int cntb = (rr == 0) ? 0 : min(c2.y, CAP);     // cdr excludes role 1

        int cc = cntc, cca = cntc + cnta;
        int T = cca + cntb;

        // warp-cooperative merge: lane p holds (e, coeff) of p-th merged entry
        int vaE = __shfl_sync(0xffffffffu, eA.x, (lane - cc) & 31);
        int vbE = __shfl_sync(0xffffffffu, eB.x, (lane - cca) & 31);
        int vaC = __shfl_sync(0xffffffffu, eA.y, (lane - cc) & 31);
        int vbC = __shfl_sync(0xffffffffu, eB.y, (lane - cca) & 31);
        int meE = (lane < cc) ? cons.x : ((lane < cca) ? vaE : vbE);
        int meC = (lane < cc) ? cons.y : ((lane < cca) ? vaC : vbC);

        float4 a = make_float4(0.f, 0.f, 0.f, 0.f);

        int Tm = min(T, 32);
        #pragma unroll 1
        for (int p = 0; p < Tm; p += 4) {
            int e0 = __shfl_sync(0xffffffffu, meE, p);
            int e1 = __shfl_sync(0xffffffffu, meE, (p + 1) & 31);
            int e2 = __shfl_sync(0xffffffffu, meE, (p + 2) & 31);
            int e3 = __shfl_sync(0xffffffffu, meE, (p + 3) & 31);
            int c0 = __shfl_sync(0xffffffffu, meC, p);
            int c1 = __shfl_sync(0xffffffffu, meC, (p + 1) & 31);
            int c2_ = __shfl_sync(0xffffffffu, meC, (p + 2) & 31);
            int c3 = __shfl_sync(0xffffffffu, meC, (p + 3) & 31);
            bool h1 = p + 1 < Tm, h2 = p + 2 < Tm, h3 = p + 3 < Tm;
            float4 v0, v1, v2, v3;
            v0 = __ldg(mem + (size_t)e0 * (FF/4) + lane);
            if (h1) v1 = __ldg(mem + (size_t)e1 * (FF/4) + lane);
            if (h2) v2 = __ldg(mem + (size_t)e2 * (FF/4) + lane);
            if (h3) v3 = __ldg(mem + (size_t)e3 * (FF/4) + lane);
            acc_fma(a, __int_as_float(c0), v0);
            if (h1) acc_fma(a, __int_as_float(c1), v1);
            if (h2) acc_fma(a, __int_as_float(c2_), v2);
            if (h3) acc_fma(a, __int_as_float(c3), v3);
        }
        // fallback tail for T>32 (each individual list <= 32; prob ~0)
        #pragma unroll 1
        for (int p = 32; p < T; p++) {
            int2 ent;
            if (p < cc)       ent = __ldg(consList + gc * CAP + p);
            else if (p < cca) ent = __ldg(&g_ac[sbA + (p - cc)]);
            else              ent = __ldg(&g_ac[sbB + (p - cca)]);
            float4 v = __ldg(mem + (size_t)ent.x * (FF/4) + lane);
            acc_fma(a, __int_as_float(ent.y), v);
        }

        if (rr == 1) {
            float d2 = __ldg(op_dist + b * 3 + 2);
            float4 rf = __ldg(root_filler + b * (FF / 4) + lane);
            acc_fma(a, d2, rf);
        }
        __stcs(out + ((size_t)(gbase + rr)) * (FF / 4) + lane, a);
    } else {
        // ---------------- high pair: rows 2k, 2k+1, k in [H/2, H) ----------------
        int t = wid - BB * HH;
        int b = t >> 10;
        int k = (HH / 2) + (t & 1023);
        int g = (b << 12) + k;
        int cnt = min(__ldg(&g_cnt[g]), CAP);
        int2 pe = __ldg(&g_ce[g * CAP + lane]);
        int2 po = __ldg(&g_co[g * CAP + lane]);

        float4 a0 = make_float4(0.f, 0.f, 0.f, 0.f);
        float4 a1 = make_float4(0.f, 0.f, 0.f, 0.f);
        #pragma unroll 1
        for (int i = 0; i < cnt; i += 4) {
            int e0 = __shfl_sync(0xffffffffu, pe.x, i);
            int e1 = __shfl_sync(0xffffffffu, pe.x, (i + 1) & 31);
            int e2 = __shfl_sync(0xffffffffu, pe.x, (i + 2) & 31);
            int e3 = __shfl_sync(0xffffffffu, pe.x, (i + 3) & 31);
            int z0 = __shfl_sync(0xffffffffu, pe.y, i);
            int z1 = __shfl_sync(0xffffffffu, pe.y, (i + 1) & 31);
            int z2 = __shfl_sync(0xffffffffu, pe.y, (i + 2) & 31);
            int z3 = __shfl_sync(0xffffffffu, pe.y, (i + 3) & 31);
            int w0 = __shfl_sync(0xffffffffu, po.y, i);
            int w1 = __shfl_sync(0xffffffffu, po.y, (i + 1) & 31);
            int w2 = __shfl_sync(0xffffffffu, po.y, (i + 2) & 31);
            int w3 = __shfl_sync(0xffffffffu, po.y, (i + 3) & 31);
            bool h1 = i + 1 < cnt, h2 = i + 2 < cnt, h3 = i + 3 < cnt;
            float4 v0, v1, v2, v3;
            v0 = __ldg(mem + (size_t)e0 * (FF/4) + lane);
            if (h1) v1 = __ldg(mem + (size_t)e1 * (FF/4) + lane);
            if (h2) v2 = __ldg(mem + (size_t)e2 * (FF/4) + lane);
            if (h3) v3 = __ldg(mem + (size_t)e3 * (FF/4) + lane);
            acc_fma(a0, __int_as_float(z0), v0); acc_fma(a1, __int_as_float(w0), v0);
            if (h1) { acc_fma(a0, __int_as_float(z1), v1); acc_fma(a1, __int_as_float(w1), v1); }
            if (h2) { acc_fma(a0, __int_as_float(z2), v2); acc_fma(a1, __int_as_float(w2), v2); }
            if (h3) { acc_fma(a0, __int_as_float(z3), v3); acc_fma(a1, __int_as_float(w3), v3); }
        }
        size_t o = ((size_t)((b << 12) + 2 * k)) * (FF / 4) + lane;
        __stcs(out + o, a0);
        __stcs(out + o + (FF / 4), a1);
    }
}

// ---------------------------------------------------------------------------
extern "C" void kernel_launch(void* const* d_in, const int* in_sizes, int n_in,
                              void* d_out, int out_size) {
    const float* mem = (const float*)d_in[0];
    const float* aw  = (const float*)d_in[1];
    const float* rf  = (const float*)d_in[2];
    const float* od  = (const float*)d_in[3];
    const int* bi    = (const int*)d_in[4];
    const int* si    = (const int*)d_in[5];
    const int* ri    = (const int*)d_in[6];
    float4* out      = (float4*)d_out;

    int n = in_sizes[4];

    void* cnt_ptr = nullptr;
    cudaGetSymbolAddress(&cnt_ptr, g_cnt);
    cudaMemsetAsync(cnt_ptr, 0, NGROUPS * sizeof(int), 0);

    dti_build_kernel<<<(n + 255) / 256, 256>>>((const float4*)aw, od, bi, si, ri, n);

    int total_warps = BB * HH + BB * (HH / 2);   // 98304
    dti_out_kernel<<<total_warps * 32 / 256, 256>>>(
        (const float4*)mem, (const float4*)rf, od, out);
}

// round 9
// speedup vs baseline: 1.3694x; 1.3694x over previous
#include <cuda_runtime.h>
#include <cstdint>

#define BB 32
#define LL 128
#define FF 128
#define RR 4096
#define HH (RR >> 1)
#define NROWS (BB * RR)        // 131072 output rows
#define CAPR 32                // per-row list capacity (mean ~4-6; P(overflow) ~ 1e-16)

// Scratch (allocation-free: __device__ globals).  131072*32*8 = 32 MB.
__device__ int  g_rcnt[NROWS];
__device__ int2 g_rlist[NROWS * CAPR];   // (element_id, coeff_bits)

__device__ __forceinline__ void acc_fma(float4& a, float c, const float4& v) {
    a.x = fmaf(c, v.x, a.x); a.y = fmaf(c, v.y, a.y);
    a.z = fmaf(c, v.z, a.z); a.w = fmaf(c, v.w, a.w);
}

__device__ __forceinline__ void append(int row, int e, float c) {
    int pos = atomicAdd(&g_rcnt[row], 1);
    if (pos < CAPR) g_rlist[row * CAPR + pos] = make_int2(e, __float_as_int(c));
}

// ---------------------------------------------------------------------------
// Kernel 1: one thread per element — append (e, coeff) to each consumer row.
//   car : j even          -> row j/2        coeff d0*w0
//   cdr : j odd, j >= 3   -> row (j-1)/2    coeff d1*w1
//   cons: j < H           -> row 2j (d2*w2) and row 2j+1 (d2*w3)
__global__ void dti_build_kernel(const float4* __restrict__ arg_w,
                                 const float*  __restrict__ op_dist,
                                 const int* __restrict__ batch_idx,
                                 const int* __restrict__ slot_idx,
                                 const int* __restrict__ role_idx,
                                 int n) {
    int e = blockIdx.x * blockDim.x + threadIdx.x;
    if (e >= n) return;
    int b = __ldg(batch_idx + e);
    int s = __ldg(slot_idx + e);
    int j = __ldg(role_idx + e);
    float4 w = __ldg(arg_w + b * LL + s);
    float d0 = __ldg(op_dist + b * 3 + 0);
    float d1 = __ldg(op_dist + b * 3 + 1);
    float d2 = __ldg(op_dist + b * 3 + 2);
    int rbase = b << 12;

    if (!(j & 1)) {
        append(rbase + (j >> 1), e, d0 * w.x);          // car
    } else if (j >= 3) {
        append(rbase + ((j - 1) >> 1), e, d1 * w.y);    // cdr
    }
    if (j < HH) {
        append(rbase + 2 * j,     e, d2 * w.z);         // cons even row
        append(rbase + 2 * j + 1, e, d2 * w.w);         // cons odd row
    }
}

// ---------------------------------------------------------------------------
// Kernel 2: ONE WARP PER OUTPUT ROW; single flat list per row.
// Lane l owns features [4l, 4l+4). Dependency chain: (cnt | list) -> values.
__global__ __launch_bounds__(256, 5)
void dti_out_kernel(const float4* __restrict__ mem,
                    const float4* __restrict__ root_filler,
                    const float*  __restrict__ op_dist,
                    float4* __restrict__ out) {
    int r = (blockIdx.x * blockDim.x + threadIdx.x) >> 5;   // row id, < NROWS
    int lane = threadIdx.x & 31;

    int cnt = min(__ldg(&g_rcnt[r]), CAPR);
    int2 ent = make_int2(0, 0);
    if (lane < cnt) ent = __ldg(&g_rlist[r * CAPR + lane]);  // coalesced

    float4 a = make_float4(0.f, 0.f, 0.f, 0.f);

    #pragma unroll 1
    for (int i = 0; i < cnt; i += 4) {
        int e0 = __shfl_sync(0xffffffffu, ent.x, i);
        int e1 = __shfl_sync(0xffffffffu, ent.x, (i + 1) & 31);
        int e2 = __shfl_sync(0xffffffffu, ent.x, (i + 2) & 31);
        int e3 = __shfl_sync(0xffffffffu, ent.x, (i + 3) & 31);
        int c0 = __shfl_sync(0xffffffffu, ent.y, i);
        int c1 = __shfl_sync(0xffffffffu, ent.y, (i + 1) & 31);
        int c2 = __shfl_sync(0xffffffffu, ent.y, (i + 2) & 31);
        int c3 = __shfl_sync(0xffffffffu, ent.y, (i + 3) & 31);
        bool h1 = i + 1 < cnt, h2 = i + 2 < cnt, h3 = i + 3 < cnt;
        float4 v0, v1, v2, v3;
        v0 = __ldg(mem + (size_t)e0 * (FF / 4) + lane);
        if (h1) v1 = __ldg(mem + (size_t)e1 * (FF / 4) + lane);
        if (h2) v2 = __ldg(mem + (size_t)e2 * (FF / 4) + lane);
        if (h3) v3 = __ldg(mem + (size_t)e3 * (FF / 4) + lane);
        acc_fma(a, __int_as_float(c0), v0);
        if (h1) acc_fma(a, __int_as_float(c1), v1);
        if (h2) acc_fma(a, __int_as_float(c2), v2);
        if (h3) acc_fma(a, __int_as_float(c3), v3);
    }

    if ((r & (RR - 1)) == 1) {      // row 1 of each batch: += d2 * root_filler[b]
        int b = r >> 12;
        float d2 = __ldg(op_dist + b * 3 + 2);
        float4 rf = __ldg(root_filler + b * (FF / 4) + lane);
        acc_fma(a, d2, rf);
    }

    __stcs(out + (size_t)r * (FF / 4) + lane, a);
}

// ---------------------------------------------------------------------------
extern "C" void kernel_launch(void* const* d_in, const int* in_sizes, int n_in,
                              void* d_out, int out_size) {
    const float* mem = (const float*)d_in[0];
    const float* aw  = (const float*)d_in[1];
    const float* rf  = (const float*)d_in[2];
    const float* od  = (const float*)d_in[3];
    const int* bi    = (const int*)d_in[4];
    const int* si    = (const int*)d_in[5];
    const int* ri    = (const int*)d_in[6];
    float4* out      = (float4*)d_out;

    int n = in_sizes[4];

    void* cnt_ptr = nullptr;
    cudaGetSymbolAddress(&cnt_ptr, g_rcnt);
    cudaMemsetAsync(cnt_ptr, 0, NROWS * sizeof(int), 0);

    dti_build_kernel<<<(n + 255) / 256, 256>>>((const float4*)aw, od, bi, si, ri, n);

    dti_out_kernel<<<NROWS * 32 / 256, 256>>>(
        (const float4*)mem, (const float4*)rf, od, out);
}

// round 10
// speedup vs baseline: 1.4129x; 1.0317x over previous
#include <cuda_runtime.h>
#include <cstdint>

#define BB 32
#define LL 128
#define FF 128
#define RR 4096
#define HH (RR >> 1)
#define NROWS (BB * RR)        // 131072 output rows
#define CAPR 32                // per-row list capacity (mean ~6 low rows; P(overflow) ~ 1e-15)

// Scratch (allocation-free: __device__ globals).  131072*32*8 = 32 MB.
__device__ int  g_rcnt[NROWS];
__device__ int2 g_rlist[NROWS * CAPR];   // (element_id, coeff_bits)

__device__ __forceinline__ void acc_fma(float4& a, float c, const float4& v) {
    a.x = fmaf(c, v.x, a.x); a.y = fmaf(c, v.y, a.y);
    a.z = fmaf(c, v.z, a.z); a.w = fmaf(c, v.w, a.w);
}

__device__ __forceinline__ void append(int row, int e, float c) {
    int pos = atomicAdd(&g_rcnt[row], 1);
    if (pos < CAPR) g_rlist[row * CAPR + pos] = make_int2(e, __float_as_int(c));
}

// ---------------------------------------------------------------------------
// Kernel 1: one thread per element — append (e, coeff) to each consumer row.
//   car : j even          -> row j/2        coeff d0*w0
//   cdr : j odd, j >= 3   -> row (j-1)/2    coeff d1*w1
//   cons: j < H           -> row 2j (d2*w2) and row 2j+1 (d2*w3)
__global__ void dti_build_kernel(const float4* __restrict__ arg_w,
                                 const float*  __restrict__ op_dist,
                                 const int* __restrict__ batch_idx,
                                 const int* __restrict__ slot_idx,
                                 const int* __restrict__ role_idx,
                                 int n) {
    int e = blockIdx.x * blockDim.x + threadIdx.x;
    if (e >= n) return;
    int b = __ldg(batch_idx + e);
    int s = __ldg(slot_idx + e);
    int j = __ldg(role_idx + e);
    float4 w = __ldg(arg_w + b * LL + s);
    float d0 = __ldg(op_dist + b * 3 + 0);
    float d1 = __ldg(op_dist + b * 3 + 1);
    float d2 = __ldg(op_dist + b * 3 + 2);
    int rbase = b << 12;

    if (!(j & 1)) {
        append(rbase + (j >> 1), e, d0 * w.x);          // car
    } else if (j >= 3) {
        append(rbase + ((j - 1) >> 1), e, d1 * w.y);    // cdr
    }
    if (j < HH) {
        append(rbase + 2 * j,     e, d2 * w.z);         // cons even row
        append(rbase + 2 * j + 1, e, d2 * w.w);         // cons odd row
    }
}

// ---------------------------------------------------------------------------
// Kernel 2: ONE WARP PER OUTPUT ROW; single flat list per row.
// Lane l owns features [4l, 4l+4).
// Dependency chain: (cnt || list) -> values.  The list load is UNCONDITIONAL
// (always in-bounds; lanes >= cnt hold garbage the loop never consumes) so it
// issues in parallel with the count load.
__global__ __launch_bounds__(256, 6)
void dti_out_kernel(const float4* __restrict__ mem,
                    const float4* __restrict__ root_filler,
                    const float*  __restrict__ op_dist,
                    float4* __restrict__ out) {
    int r = (blockIdx.x * blockDim.x + threadIdx.x) >> 5;   // row id, < NROWS
    int lane = threadIdx.x & 31;

    int cnt = __ldg(&g_rcnt[r]);                            // level-1a
    int2 ent = __ldg(&g_rlist[r * CAPR + lane]);            // level-1b (parallel)
    cnt = min(cnt, CAPR);

    float4 a = make_float4(0.f, 0.f, 0.f, 0.f);

    #pragma unroll 1
    for (int i = 0; i < cnt; i += 4) {
        int e0 = __shfl_sync(0xffffffffu, ent.x, i);
        int e1 = __shfl_sync(0xffffffffu, ent.x, (i + 1) & 31);
        int e2 = __shfl_sync(0xffffffffu, ent.x, (i + 2) & 31);
        int e3 = __shfl_sync(0xffffffffu, ent.x, (i + 3) & 31);
        int c0 = __shfl_sync(0xffffffffu, ent.y, i);
        int c1 = __shfl_sync(0xffffffffu, ent.y, (i + 1) & 31);
        int c2 = __shfl_sync(0xffffffffu, ent.y, (i + 2) & 31);
        int c3 = __shfl_sync(0xffffffffu, ent.y, (i + 3) & 31);
        bool h1 = i + 1 < cnt, h2 = i + 2 < cnt, h3 = i + 3 < cnt;
        float4 v0, v1, v2, v3;
        v0 = __ldg(mem + (size_t)e0 * (FF / 4) + lane);
        if (h1) v1 = __ldg(mem + (size_t)e1 * (FF / 4) + lane);
        if (h2) v2 = __ldg(mem + (size_t)e2 * (FF / 4) + lane);
        if (h3) v3 = __ldg(mem + (size_t)e3 * (FF / 4) + lane);
        acc_fma(a, __int_as_float(c0), v0);
        if (h1) acc_fma(a, __int_as_float(c1), v1);
        if (h2) acc_fma(a, __int_as_float(c2), v2);
        if (h3) acc_fma(a, __int_as_float(c3), v3);
    }

    if ((r & (RR - 1)) == 1) {      // row 1 of each batch: += d2 * root_filler[b]
        int b = r >> 12;
        float d2 = __ldg(op_dist + b * 3 + 2);
        float4 rf = __ldg(root_filler + b * (FF / 4) + lane);
        acc_fma(a, d2, rf);
    }

    __stcs(out + (size_t)r * (FF / 4) + lane, a);
}

// ---------------------------------------------------------------------------
extern "C" void kernel_launch(void* const* d_in, const int* in_sizes, int n_in,
                              void* d_out, int out_size) {
    const float* mem = (const float*)d_in[0];
    const float* aw  = (const float*)d_in[1];
    const float* rf  = (const float*)d_in[2];
    const float* od  = (const float*)d_in[3];
    const int* bi    = (const int*)d_in[4];
    const int* si    = (const int*)d_in[5];
    const int* ri    = (const int*)d_in[6];
    float4* out      = (float4*)d_out;

    int n = in_sizes[4];

    void* cnt_ptr = nullptr;
    cudaGetSymbolAddress(&cnt_ptr, g_rcnt);
    cudaMemsetAsync(cnt_ptr, 0, NROWS * sizeof(int), 0);

    dti_build_kernel<<<(n + 511) / 512, 512>>>((const float4*)aw, od, bi, si, ri, n);

    dti_out_kernel<<<NROWS * 32 / 256, 256>>>(
        (const float4*)mem, (const float4*)rf, od, out);
}